// round 1
// baseline (speedup 1.0000x reference)
#include <cuda_runtime.h>

// LIF spiking neuron: T=4, THRESH=1.0, TAU=1.0 (so mem*tau + x == mem + x).
// x: [T=4, N=8388608] float32, out spikes: same shape float32.
// Recurrence per spatial slot:
//   mem += x[t]; spike = (mem - 1 > 0); mem = (1 - spike) * mem
// Each thread handles 4 contiguous floats (float4) across all T steps.

__global__ void __launch_bounds__(256) lif_spike_kernel(
    const float4* __restrict__ x,
    float4* __restrict__ out,
    int n4)   // number of float4 per timestep (8388608/4 = 2097152)
{
    int i = blockIdx.x * blockDim.x + threadIdx.x;
    if (i >= n4) return;

    // Load all 4 timesteps up-front: independent loads -> MLP=4
    float4 x0 = x[i];
    float4 x1 = x[i + n4];
    float4 x2 = x[i + 2 * n4];
    float4 x3 = x[i + 3 * n4];

    float4 mem = make_float4(0.f, 0.f, 0.f, 0.f);
    float4 s;

    // t = 0
    mem.x += x0.x; mem.y += x0.y; mem.z += x0.z; mem.w += x0.w;
    s.x = (mem.x > 1.0f) ? 1.0f : 0.0f;
    s.y = (mem.y > 1.0f) ? 1.0f : 0.0f;
    s.z = (mem.z > 1.0f) ? 1.0f : 0.0f;
    s.w = (mem.w > 1.0f) ? 1.0f : 0.0f;
    out[i] = s;
    mem.x = (s.x > 0.f) ? 0.f : mem.x;
    mem.y = (s.y > 0.f) ? 0.f : mem.y;
    mem.z = (s.z > 0.f) ? 0.f : mem.z;
    mem.w = (s.w > 0.f) ? 0.f : mem.w;

    // t = 1
    mem.x += x1.x; mem.y += x1.y; mem.z += x1.z; mem.w += x1.w;
    s.x = (mem.x > 1.0f) ? 1.0f : 0.0f;
    s.y = (mem.y > 1.0f) ? 1.0f : 0.0f;
    s.z = (mem.z > 1.0f) ? 1.0f : 0.0f;
    s.w = (mem.w > 1.0f) ? 1.0f : 0.0f;
    out[i + n4] = s;
    mem.x = (s.x > 0.f) ? 0.f : mem.x;
    mem.y = (s.y > 0.f) ? 0.f : mem.y;
    mem.z = (s.z > 0.f) ? 0.f : mem.z;
    mem.w = (s.w > 0.f) ? 0.f : mem.w;

    // t = 2
    mem.x += x2.x; mem.y += x2.y; mem.z += x2.z; mem.w += x2.w;
    s.x = (mem.x > 1.0f) ? 1.0f : 0.0f;
    s.y = (mem.y > 1.0f) ? 1.0f : 0.0f;
    s.z = (mem.z > 1.0f) ? 1.0f : 0.0f;
    s.w = (mem.w > 1.0f) ? 1.0f : 0.0f;
    out[i + 2 * n4] = s;
    mem.x = (s.x > 0.f) ? 0.f : mem.x;
    mem.y = (s.y > 0.f) ? 0.f : mem.y;
    mem.z = (s.z > 0.f) ? 0.f : mem.z;
    mem.w = (s.w > 0.f) ? 0.f : mem.w;

    // t = 3 (no membrane update needed after last spike)
    mem.x += x3.x; mem.y += x3.y; mem.z += x3.z; mem.w += x3.w;
    s.x = (mem.x > 1.0f) ? 1.0f : 0.0f;
    s.y = (mem.y > 1.0f) ? 1.0f : 0.0f;
    s.z = (mem.z > 1.0f) ? 1.0f : 0.0f;
    s.w = (mem.w > 1.0f) ? 1.0f : 0.0f;
    out[i + 3 * n4] = s;
}

extern "C" void kernel_launch(void* const* d_in, const int* in_sizes, int n_in,
                              void* d_out, int out_size)
{
    const float4* x = (const float4*)d_in[0];
    float4* out = (float4*)d_out;

    // in_sizes[0] = T * N = 4 * 8388608 total floats
    int total = in_sizes[0];
    int n_per_t = total / 4;       // elements per timestep
    int n4 = n_per_t / 4;          // float4 per timestep

    int threads = 256;
    int blocks = (n4 + threads - 1) / threads;
    lif_spike_kernel<<<blocks, threads>>>(x, out, n4);
}